// round 6
// baseline (speedup 1.0000x reference)
#include <cuda_runtime.h>
#include <cuda_bf16.h>
#include <cstddef>

// WKV2D: B=8, H=16, W=16, C=256.
// k_adj = sum_taps relu(k - w[c]*manhattan_d) (+u bonus at center); out = exp(k_adj)*v.
// Sparsity: taps with d > r = floor(kmax_c/w_c)+1 are exactly zero (w>0, kmax over FULL image).
// Halo trick: -1e30 padding => relu gives exact 0, no bounds checks in the fast path.
//
// Block = 8 consecutive channels x half image (8 rows) of one batch; 512 threads, 2px/thread.
// Lane map c = t&7 -> every global access is a fully-utilized 32B sector.

#define B_DIM   8
#define C_DIM   256
#define CCH     8
#define PAD     3            // fast path covers r <= 3
#define TW      23           // padded row stride
#define TROWS   14           // 8 output rows + 2*PAD
#define CPLANE  325          // 322 used; 325 % 32 == 5 -> conflict-free tap LDS

__device__ __forceinline__ float relu_(float x) { return fmaxf(x, 0.0f); }

// 2 adjacent pixels of one channel, compile-time radius; row segments shared.
template<int R>
__device__ __forceinline__ void diamond2(const float* __restrict__ ksb, int pos0,
                                         float wneg, float acc[2])
{
    float wd[2 * R + 1];
    #pragma unroll
    for (int d = 0; d <= 2 * R; ++d) wd[d] = wneg * (float)d;

    #pragma unroll
    for (int di = -R; di <= R; ++di) {
        const int adi = di < 0 ? -di : di;
        const int rr  = R - adi;
        float seg[2 + 2 * R];
        const int sbase = pos0 + di * TW - rr;
        #pragma unroll
        for (int j = 0; j < 2 + 2 * rr; ++j) seg[j] = ksb[sbase + j];
        #pragma unroll
        for (int i = 0; i < 2; ++i) {
            #pragma unroll
            for (int dj = -rr; dj <= rr; ++dj) {
                const int adj = dj < 0 ? -dj : dj;
                acc[i] += relu_(seg[i + dj + rr] + wd[adi + adj]);
            }
        }
    }
}

__global__ __launch_bounds__(512, 4)
void wkv2d_kernel(const float* __restrict__ w,
                  const float* __restrict__ u,
                  const float* __restrict__ k,
                  const float* __restrict__ v,
                  float* __restrict__ out)
{
    __shared__ float ks[CCH * CPLANE];              // 8 padded half-planes (~10.4KB)
    __shared__ __align__(16) float red[CCH * 16];   // [c][warp] partial maxes

    const int bid   = blockIdx.x;
    const int b     = bid >> 6;
    const int chunk = (bid >> 1) & 31;
    const int h     = bid & 1;                      // image half
    const int c0    = chunk * CCH;
    const int t     = threadIdx.x;
    const int c     = t & 7;
    const int s     = t >> 3;                       // 0..63
    const int yl    = s >> 3;                       // 0..7 local output row
    const int x0    = (s & 7) << 1;

    const size_t base = ((size_t)b * 256) * C_DIM + c0;
    const int y   = h * 8 + yl;                     // global output row
    const int px0 = (y << 4) + x0;

    // ---- v prefetch (independent of everything) ----
    const float v0 = v[base + (size_t)px0 * C_DIM + c];
    const float v1 = v[base + (size_t)(px0 + 1) * C_DIM + c];
    const float wv = w[c0 + c];
    const float uv = u[c0 + c];

    // ---- tile load: 14 rows x 16 px x 8 ch; vertical halo -> -1e30 ----
    const int row0 = h * 8 - PAD;                   // global row of tile row 0
    float mloc = -1e30f;
    #pragma unroll
    for (int j = 0; j < 4; ++j) {
        int i = t + 512 * j;                        // i&7 == c
        if (i < TROWS * 128) {
            int rl  = i >> 7;
            int xx  = (i >> 3) & 15;
            int rg  = row0 + rl;
            float val = -1e30f;
            if ((unsigned)rg < 16u)
                val = k[base + (size_t)((rg << 4) + xx) * C_DIM + c];
            mloc = fmaxf(mloc, val);
            ks[c * CPLANE + rl * TW + xx + PAD] = val;
        }
    }

    // ---- the 5 rows outside the slab feed ONLY the max (exactness of r) ----
    const int er0 = h ? 0 : 11;
    #pragma unroll
    for (int j = 0; j < 2; ++j) {
        int i = t + 512 * j;
        if (i < 5 * 128) {
            int rl = i >> 7;
            int xx = (i >> 3) & 15;
            mloc = fmaxf(mloc, k[base + (size_t)(((er0 + rl) << 4) + xx) * C_DIM + c]);
        }
    }

    // ---- column halo fill (6 cols x 14 rows x 8 planes = 672) ----
    #pragma unroll
    for (int j = 0; j < 2; ++j) {
        int i = t + 512 * j;
        if (i < 672) {
            int p   = i / 84;
            int rem = i - p * 84;
            int rr  = rem / 6;
            int ci  = rem - rr * 6;
            int col = ci < 3 ? ci : 16 + ci;
            ks[p * CPLANE + rr * TW + col] = -1e30f;
        }
    }

    // ---- per-channel max: lanes with same c are xor 8,16 apart ----
    mloc = fmaxf(mloc, __shfl_xor_sync(0xffffffffu, mloc, 8));
    mloc = fmaxf(mloc, __shfl_xor_sync(0xffffffffu, mloc, 16));
    if ((t & 31) < 8) red[c * 16 + (t >> 5)] = mloc;

    __syncthreads();   // single barrier: tile + halo + red all visible

    const float4 ra = *(const float4*)&red[c * 16];
    const float4 rb = *(const float4*)&red[c * 16 + 4];
    const float4 rc4 = *(const float4*)&red[c * 16 + 8];
    const float4 rd = *(const float4*)&red[c * 16 + 12];
    float mm = fmaxf(fmaxf(fmaxf(ra.x, ra.y), fmaxf(ra.z, ra.w)),
                     fmaxf(fmaxf(rb.x, rb.y), fmaxf(rb.z, rb.w)));
    mm = fmaxf(mm, fmaxf(fmaxf(fmaxf(rc4.x, rc4.y), fmaxf(rc4.z, rc4.w)),
                         fmaxf(fmaxf(rd.x, rd.y), fmaxf(rd.z, rd.w))));

    int rch = (int)__fdividef(fmaxf(mm, 0.0f), wv) + 1;  // taps with d > rch are exactly 0
    rch = min(rch, 30);
    const int r = __reduce_max_sync(0xffffffffu, rch);   // warp max == block max (all 8 c per warp)

    const float wneg = -wv;
    const float* ksb = ks + c * CPLANE;
    const int pos0 = (yl + PAD) * TW + (x0 + PAD);

    // ---- center bonus init: relu(k+u) replaces relu(k) ----
    const float kc0 = ksb[pos0], kc1 = ksb[pos0 + 1];
    float acc[2];
    acc[0] = relu_(kc0 + uv) - relu_(kc0);
    acc[1] = relu_(kc1 + uv) - relu_(kc1);

    if (r <= PAD) {
        switch (r) {
            case 1:  diamond2<1>(ksb, pos0, wneg, acc); break;
            case 2:  diamond2<2>(ksb, pos0, wneg, acc); break;
            default: diamond2<3>(ksb, pos0, wneg, acc); break;
        }
    } else {
        // generic fallback: bounds-checked reads straight from global (rare)
        #pragma unroll
        for (int i = 0; i < 2; ++i) {
            const int xx = x0 + i;
            float a = acc[i];
            for (int di = -r; di <= r; ++di) {
                int iy = y + di;
                if ((unsigned)iy >= 16u) continue;
                int adi = di < 0 ? -di : di;
                int rr = r - adi;
                for (int dj = -rr; dj <= rr; ++dj) {
                    int ix = xx + dj;
                    if ((unsigned)ix >= 16u) continue;
                    int adj_ = dj < 0 ? -dj : dj;
                    a += relu_(fmaf(wneg, (float)(adi + adj_),
                                    k[base + (size_t)((iy << 4) + ix) * C_DIM + c]));
                }
            }
            acc[i] = a;
        }
    }

    // ---- epilogue: fully-sectored stores ----
    out[base + (size_t)px0 * C_DIM + c]       = __expf(acc[0]) * v0;
    out[base + (size_t)(px0 + 1) * C_DIM + c] = __expf(acc[1]) * v1;
}

extern "C" void kernel_launch(void* const* d_in, const int* in_sizes, int n_in,
                              void* d_out, int out_size)
{
    const float *w = nullptr, *u = nullptr, *k = nullptr, *v = nullptr;
    for (int i = 0; i < n_in; i++) {
        if (in_sizes[i] == C_DIM) {
            if (!w) w = (const float*)d_in[i];
            else if (!u) u = (const float*)d_in[i];
        } else if (in_sizes[i] == B_DIM * 256 * C_DIM) {
            if (!k) k = (const float*)d_in[i];
            else if (!v) v = (const float*)d_in[i];
        }
    }
    wkv2d_kernel<<<B_DIM * 64, 512>>>(w, u, k, v, (float*)d_out);
}

// round 7
// speedup vs baseline: 1.5556x; 1.5556x over previous
#include <cuda_runtime.h>
#include <cuda_bf16.h>
#include <cstddef>

// WKV2D: B=8, H=16, W=16, C=256.
// k_adj = sum_taps relu(k - w[c]*manhattan_d) (+u bonus at center); out = exp(k_adj)*v.
// Sparsity: taps with d > r = floor(kmax_c/w_c)+1 are exactly zero (w>0).
// Halo trick: -1e30 padding => relu gives exact 0, no bounds checks in fast path.
//
// Block = 8 consecutive channels x whole 16x16 image of one batch; 256 threads.
// Thread (c = t&7, s = t>>3) owns 8 horizontally-consecutive pixels of one
// channel -> every global access is a fully-utilized 32B sector.

#define B_DIM   8
#define C_DIM   256
#define CCH     8
#define PAD     3            // fast path covers r <= 3
#define TW      23           // padded row stride
#define TROWS   22           // 16 + 2*PAD
#define CPLANE  516          // 506 used

__device__ __forceinline__ float relu_(float x) { return fmaxf(x, 0.0f); }

// 8 consecutive pixels of one channel, compile-time radius.
// Each tap-row segment is loaded once into registers and serves all 8 pixels.
template<int R>
__device__ __forceinline__ void diamond8(const float* __restrict__ ksb, int pos0,
                                         float wneg, float acc[8])
{
    float wd[2 * R + 1];
    #pragma unroll
    for (int d = 0; d <= 2 * R; ++d) wd[d] = wneg * (float)d;

    #pragma unroll
    for (int di = -R; di <= R; ++di) {
        const int adi = di < 0 ? -di : di;
        const int rr  = R - adi;
        float seg[8 + 2 * R];
        const int sbase = pos0 + di * TW - rr;
        #pragma unroll
        for (int j = 0; j < 8 + 2 * rr; ++j) seg[j] = ksb[sbase + j];
        #pragma unroll
        for (int i = 0; i < 8; ++i) {
            #pragma unroll
            for (int dj = -rr; dj <= rr; ++dj) {
                const int adj = dj < 0 ? -dj : dj;
                acc[i] += relu_(seg[i + dj + rr] + wd[adi + adj]);
            }
        }
    }
}

__global__ __launch_bounds__(256, 4)
void wkv2d_kernel(const float* __restrict__ w,
                  const float* __restrict__ u,
                  const float* __restrict__ k,
                  const float* __restrict__ v,
                  float* __restrict__ out)
{
    __shared__ float ks[CCH * CPLANE];              // 8 padded channel planes (~16.5KB)
    __shared__ __align__(16) float red[CCH * 8];    // [c][warp] partial maxes

    const int b  = blockIdx.x >> 5;      // 32 channel-chunks per batch
    const int c0 = (blockIdx.x & 31) * CCH;
    const int t  = threadIdx.x;
    const int c  = t & 7;
    const int s  = t >> 3;               // 0..31 : (y, half-row)
    const int y  = s >> 1;
    const int x0 = (s & 1) << 3;

    const size_t base = ((size_t)b * 256) * C_DIM + c0;
    const float* kg = k + base + c;
    const float* vg = v + base + c;
    const int px0 = (y << 4) + x0;

    // ---- issue all 16 global loads up front (MLP) ----
    float kr[8], vr[8];
    #pragma unroll
    for (int i = 0; i < 8; ++i) kr[i] = kg[(size_t)(px0 + i) * C_DIM];
    #pragma unroll
    for (int i = 0; i < 8; ++i) vr[i] = vg[(size_t)(px0 + i) * C_DIM];

    const float wv = w[c0 + c];
    const float uv = u[c0 + c];

    // ---- halo-only fill: 250 halo cells/plane, one per thread per plane ----
    // halo rows: 0,1,2,19,20,21 full (6*23=138); rows 3..18 cols {0,1,2,19..22} (16*7=112)
    if (t < 250) {
        int row, col;
        if (t < 138) {
            int r6 = t / 23;
            col = t - r6 * 23;
            row = r6 < 3 ? r6 : r6 + 16;
        } else {
            int q = t - 138;
            int qr = q / 7;
            int ci = q - qr * 7;
            row = 3 + qr;
            col = ci < 3 ? ci : ci + 16;
        }
        const int pos = row * TW + col;
        #pragma unroll
        for (int p = 0; p < CCH; ++p)
            ks[p * CPLANE + pos] = -1e30f;
    }

    // ---- interior stores + per-channel partial max (registers) ----
    float* ksb = ks + c * CPLANE;
    const int pos0 = (y + PAD) * TW + (x0 + PAD);
    float m = kr[0];
    #pragma unroll
    for (int i = 0; i < 8; ++i) {
        ksb[pos0 + i] = kr[i];
        if (i) m = fmaxf(m, kr[i]);
    }
    // reduce over lanes with the same channel (xor 8, 16)
    m = fmaxf(m, __shfl_xor_sync(0xffffffffu, m, 8));
    m = fmaxf(m, __shfl_xor_sync(0xffffffffu, m, 16));
    if ((t & 31) < 8) red[c * 8 + (t >> 5)] = m;

    __syncthreads();   // single barrier: tile + halo + red all visible

    const float4 ra = *(const float4*)&red[c * 8];
    const float4 rb = *(const float4*)&red[c * 8 + 4];
    float mm = fmaxf(fmaxf(fmaxf(ra.x, ra.y), fmaxf(ra.z, ra.w)),
                     fmaxf(fmaxf(rb.x, rb.y), fmaxf(rb.z, rb.w)));

    int rch = (int)__fdividef(fmaxf(mm, 0.0f), wv) + 1;  // taps with d > rch exactly 0
    rch = min(rch, 30);
    const int r = __reduce_max_sync(0xffffffffu, rch);   // warp holds all 8 c -> block max

    const float wneg = -wv;

    // ---- init acc with the center bonus (relu(k+u) replaces relu(k)) ----
    float acc[8];
    #pragma unroll
    for (int i = 0; i < 8; ++i)
        acc[i] = relu_(kr[i] + uv) - relu_(kr[i]);

    if (r <= PAD) {
        switch (r) {
            case 1:  diamond8<1>(ksb, pos0, wneg, acc); break;
            case 2:  diamond8<2>(ksb, pos0, wneg, acc); break;
            default: diamond8<3>(ksb, pos0, wneg, acc); break;
        }
    } else {
        // generic bounds-checked fallback (rare); tile holds the full image
        #pragma unroll
        for (int i = 0; i < 8; ++i) {
            const int xx = x0 + i;
            float a = acc[i];
            for (int di = -r; di <= r; ++di) {
                int iy = y + di;
                if ((unsigned)iy >= 16u) continue;
                int adi = di < 0 ? -di : di;
                int rr = r - adi;
                for (int dj = -rr; dj <= rr; ++dj) {
                    int ix = xx + dj;
                    if ((unsigned)ix >= 16u) continue;
                    int adj_ = dj < 0 ? -dj : dj;
                    a += relu_(fmaf(wneg, (float)(adi + adj_),
                                    ksb[(iy + PAD) * TW + ix + PAD]));
                }
            }
            acc[i] = a;
        }
    }

    // ---- epilogue: fully-sectored stores ----
    float* og = out + base + c;
    #pragma unroll
    for (int i = 0; i < 8; ++i)
        og[(size_t)(px0 + i) * C_DIM] = __expf(acc[i]) * vr[i];
}

extern "C" void kernel_launch(void* const* d_in, const int* in_sizes, int n_in,
                              void* d_out, int out_size)
{
    const float *w = nullptr, *u = nullptr, *k = nullptr, *v = nullptr;
    for (int i = 0; i < n_in; i++) {
        if (in_sizes[i] == C_DIM) {
            if (!w) w = (const float*)d_in[i];
            else if (!u) u = (const float*)d_in[i];
        } else if (in_sizes[i] == B_DIM * 256 * C_DIM) {
            if (!k) k = (const float*)d_in[i];
            else if (!v) v = (const float*)d_in[i];
        }
    }
    wkv2d_kernel<<<B_DIM * (C_DIM / CCH), 256>>>(w, u, k, v, (float*)d_out);
}

// round 8
// speedup vs baseline: 1.6154x; 1.0385x over previous
#include <cuda_runtime.h>
#include <cuda_bf16.h>
#include <cstddef>

// WKV2D: B=8, H=16, W=16, C=256.
// k_adj = sum_taps relu(k - w[c]*manhattan_d) (+u bonus at center); out = exp(k_adj)*v.
// Sparsity: taps with d > r = floor(kmax_c/w_c)+1 are exactly zero (w>0).
// Halo trick: -1e30 padding => relu gives exact 0, no bounds checks in fast path.
//
// Block = 8 consecutive channels x whole 16x16 image of one batch; 256 threads.
// Thread (c = t&7, s = t>>3) owns 8 horizontally-consecutive pixels of one
// channel -> every global access is a fully-utilized 32B sector.

#define B_DIM   8
#define C_DIM   256
#define CCH     8
#define PAD     2            // fast path covers r <= 2 (r>=3 falls back, ~never)
#define TW      20           // padded row stride (16 + 2*PAD)
#define TROWS   20           // 16 + 2*PAD
#define CPLANE  405          // 400 used; 405 % 32 == 21 -> near-conflict-free

__device__ __forceinline__ float relu_(float x) { return fmaxf(x, 0.0f); }

// 8 consecutive pixels of one channel, compile-time radius.
// Center tap (0,0) is EXCLUDED (handled by the u-bonus init).
// Each tap-row segment is loaded once into registers and serves all 8 pixels.
template<int R>
__device__ __forceinline__ void diamond8(const float* __restrict__ ksb, int pos0,
                                         float wneg, float acc[8])
{
    float wd[2 * R + 1];
    #pragma unroll
    for (int d = 0; d <= 2 * R; ++d) wd[d] = wneg * (float)d;

    #pragma unroll
    for (int di = -R; di <= R; ++di) {
        const int adi = di < 0 ? -di : di;
        const int rr  = R - adi;
        float seg[8 + 2 * R];
        const int sbase = pos0 + di * TW - rr;
        #pragma unroll
        for (int j = 0; j < 8 + 2 * rr; ++j) seg[j] = ksb[sbase + j];
        #pragma unroll
        for (int i = 0; i < 8; ++i) {
            #pragma unroll
            for (int dj = -rr; dj <= rr; ++dj) {
                if (di == 0 && dj == 0) continue;   // center handled in init
                const int adj = dj < 0 ? -dj : dj;
                acc[i] += relu_(seg[i + dj + rr] + wd[adi + adj]);
            }
        }
    }
}

__global__ __launch_bounds__(256, 4)
void wkv2d_kernel(const float* __restrict__ w,
                  const float* __restrict__ u,
                  const float* __restrict__ k,
                  const float* __restrict__ v,
                  float* __restrict__ out)
{
    __shared__ float ks[CCH * CPLANE];              // 8 padded channel planes (~13KB)
    __shared__ __align__(16) float red[CCH * 8];    // [c][warp] partial maxes

    const int b  = blockIdx.x >> 5;      // 32 channel-chunks per batch
    const int c0 = (blockIdx.x & 31) * CCH;
    const int t  = threadIdx.x;
    const int c  = t & 7;
    const int s  = t >> 3;               // 0..31 : (y, half-row)
    const int y  = s >> 1;
    const int x0 = (s & 1) << 3;

    const size_t base = ((size_t)b * 256) * C_DIM + c0;
    const float* kg = k + base + c;
    const float* vg = v + base + c;
    const int px0 = (y << 4) + x0;

    // ---- issue all 16 global loads up front (MLP) ----
    float kr[8], vr[8];
    #pragma unroll
    for (int i = 0; i < 8; ++i) kr[i] = kg[(size_t)(px0 + i) * C_DIM];
    #pragma unroll
    for (int i = 0; i < 8; ++i) vr[i] = vg[(size_t)(px0 + i) * C_DIM];

    const float wv = w[c0 + c];
    const float uv = u[c0 + c];

    // ---- halo-only fill: 144 halo cells/plane ----
    // rows 0,1,18,19 full (4*20=80); rows 2..17 cols {0,1,18,19} (16*4=64)
    if (t < 144) {
        int row, col;
        if (t < 80) {
            int r4 = t / 20;
            col = t - r4 * 20;
            row = r4 < 2 ? r4 : r4 + 16;
        } else {
            int q = t - 80;
            int qr = q >> 2;
            int ci = q & 3;
            row = 2 + qr;
            col = ci < 2 ? ci : ci + 16;
        }
        const int pos = row * TW + col;
        #pragma unroll
        for (int p = 0; p < CCH; ++p)
            ks[p * CPLANE + pos] = -1e30f;
    }

    // ---- interior stores + per-channel partial max (registers) ----
    float* ksb = ks + c * CPLANE;
    const int pos0 = (y + PAD) * TW + (x0 + PAD);
    float m = kr[0];
    #pragma unroll
    for (int i = 0; i < 8; ++i) {
        ksb[pos0 + i] = kr[i];
        if (i) m = fmaxf(m, kr[i]);
    }
    // reduce over lanes with the same channel (xor 8, 16)
    m = fmaxf(m, __shfl_xor_sync(0xffffffffu, m, 8));
    m = fmaxf(m, __shfl_xor_sync(0xffffffffu, m, 16));
    if ((t & 31) < 8) red[c * 8 + (t >> 5)] = m;

    __syncthreads();   // single barrier: tile + halo + red all visible

    const float4 ra = *(const float4*)&red[c * 8];
    const float4 rb = *(const float4*)&red[c * 8 + 4];
    float mm = fmaxf(fmaxf(fmaxf(ra.x, ra.y), fmaxf(ra.z, ra.w)),
                     fmaxf(fmaxf(rb.x, rb.y), fmaxf(rb.z, rb.w)));

    int rch = (int)__fdividef(fmaxf(mm, 0.0f), wv) + 1;  // taps with d > rch exactly 0
    rch = min(rch, 30);
    const int r = __reduce_max_sync(0xffffffffu, rch);   // warp holds all 8 c -> block max

    const float wneg = -wv;

    // ---- init acc with the center term: relu(k + u) (center excluded in diamond) ----
    float acc[8];
    #pragma unroll
    for (int i = 0; i < 8; ++i)
        acc[i] = relu_(kr[i] + uv);

    if (r <= PAD) {
        if (r == 1) diamond8<1>(ksb, pos0, wneg, acc);
        else        diamond8<2>(ksb, pos0, wneg, acc);
    } else {
        // generic bounds-checked fallback (essentially never taken);
        // reads only the 16x16 interior of the tile, never the halo.
        #pragma unroll
        for (int i = 0; i < 8; ++i) {
            const int xx = x0 + i;
            float a = acc[i];
            for (int di = -r; di <= r; ++di) {
                int iy = y + di;
                if ((unsigned)iy >= 16u) continue;
                int adi = di < 0 ? -di : di;
                int rr = r - adi;
                for (int dj = -rr; dj <= rr; ++dj) {
                    if (di == 0 && dj == 0) continue;
                    int ix = xx + dj;
                    if ((unsigned)ix >= 16u) continue;
                    int adj_ = dj < 0 ? -dj : dj;
                    a += relu_(fmaf(wneg, (float)(adi + adj_),
                                    ksb[(iy + PAD) * TW + ix + PAD]));
                }
            }
            acc[i] = a;
        }
    }

    // ---- epilogue: fully-sectored stores ----
    float* og = out + base + c;
    #pragma unroll
    for (int i = 0; i < 8; ++i)
        og[(size_t)(px0 + i) * C_DIM] = __expf(acc[i]) * vr[i];
}

extern "C" void kernel_launch(void* const* d_in, const int* in_sizes, int n_in,
                              void* d_out, int out_size)
{
    const float *w = nullptr, *u = nullptr, *k = nullptr, *v = nullptr;
    for (int i = 0; i < n_in; i++) {
        if (in_sizes[i] == C_DIM) {
            if (!w) w = (const float*)d_in[i];
            else if (!u) u = (const float*)d_in[i];
        } else if (in_sizes[i] == B_DIM * 256 * C_DIM) {
            if (!k) k = (const float*)d_in[i];
            else if (!v) v = (const float*)d_in[i];
        }
    }
    wkv2d_kernel<<<B_DIM * (C_DIM / CCH), 256>>>(w, u, k, v, (float*)d_out);
}